// round 9
// baseline (speedup 1.0000x reference)
#include <cuda_runtime.h>
#include <cuda_bf16.h>
#include <cstdint>

#define B_ 2
#define H_ 8
#define S_ 2048
#define D_ 64
#define BH_ (B_ * H_)
#define OUT_OFF ((size_t)B_ * H_ * S_ * D_)   // output tensor first, then weights
#define KBLK 32                                // av chunks (64 wide)
#define QBLK 16                                // stats k-blocks (128 wide)

__device__ float  g_bias_lut[H_ * 2 * S_];
__device__ float2 g_stats[BH_ * S_ * QBLK];
__device__ float2 g_rowstats[BH_ * S_];
// packed bf16 hi/lo planes
__device__ unsigned g_Qh[BH_ * S_ * 32];   // [bh][row][dpair]
__device__ unsigned g_Ql[BH_ * S_ * 32];
__device__ unsigned g_Kh[BH_ * S_ * 32];
__device__ unsigned g_Kl[BH_ * S_ * 32];
__device__ unsigned g_Vth[BH_ * KBLK * 64 * 32];   // [bh][chunk][d][kpair] (transposed)
__device__ unsigned g_Vtl[BH_ * KBLK * 64 * 32];

// ---- helpers ----------------------------------------------------------------
__device__ __forceinline__ void split_pack(float x0, float x1, unsigned& hi, unsigned& lo) {
    __nv_bfloat162 h = __floats2bfloat162_rn(x0, x1);
    float f0 = __bfloat162float(__low2bfloat16(h));
    float f1 = __bfloat162float(__high2bfloat16(h));
    __nv_bfloat162 l = __floats2bfloat162_rn(x0 - f0, x1 - f1);
    hi = *reinterpret_cast<unsigned*>(&h);
    lo = *reinterpret_cast<unsigned*>(&l);
}
__device__ __forceinline__ void mma16(float* d, const unsigned* a, const unsigned* b) {
    asm("mma.sync.aligned.m16n8k16.row.col.f32.bf16.bf16.f32 "
        "{%0,%1,%2,%3},{%4,%5,%6,%7},{%8,%9},{%0,%1,%2,%3};"
        : "+f"(d[0]), "+f"(d[1]), "+f"(d[2]), "+f"(d[3])
        : "r"(a[0]), "r"(a[1]), "r"(a[2]), "r"(a[3]), "r"(b[0]), "r"(b[1]));
}
__device__ __forceinline__ void ldm4(unsigned* r, unsigned addr) {
    asm volatile("ldmatrix.sync.aligned.m8n8.x4.shared.b16 {%0,%1,%2,%3}, [%4];"
        : "=r"(r[0]), "=r"(r[1]), "=r"(r[2]), "=r"(r[3]) : "r"(addr));
}
__device__ __forceinline__ void cpa16(unsigned dst, const void* src) {
    asm volatile("cp.async.cg.shared.global [%0], [%1], 16;" :: "r"(dst), "l"(src));
}
__device__ __forceinline__ void cpa_commit() { asm volatile("cp.async.commit_group;"); }
__device__ __forceinline__ void cpa_wait0()  { asm volatile("cp.async.wait_group 0;"); }
__device__ __forceinline__ float ex2f(float x) {
    float r; asm("ex2.approx.f32 %0, %1;" : "=f"(r) : "f"(x)); return r;
}
#define LOG2E 1.4426950408889634f
__device__ __forceinline__ float fast_exp(float x) { return ex2f(x * LOG2E); }

// ---------------------------------------------------------------------------
// Kernel 0: T5 bias LUT (exact integer bucket thresholds)
// ---------------------------------------------------------------------------
__global__ void bias_lut_kernel(const float* __restrict__ bias_table) {
    int idx = blockIdx.x * blockDim.x + threadIdx.x;
    if (idx >= H_ * 2 * S_) return;
    int h   = idx >> 12;
    int r   = idx & 4095;
    int rel = r - 2048;
    int bucket = (rel > 0) ? 16 : 0;
    int a = rel < 0 ? -rel : rel;
    int add;
    if      (a <  8) add = a;
    else if (a < 12) add = 8;
    else if (a < 16) add = 9;
    else if (a < 23) add = 10;
    else if (a < 32) add = 11;
    else if (a < 46) add = 12;
    else if (a < 64) add = 13;
    else if (a < 91) add = 14;
    else             add = 15;
    g_bias_lut[idx] = bias_table[(bucket + add) * H_ + h];
}

// ---------------------------------------------------------------------------
// Kernel 0a: Q,K -> packed row-major bf16 hi/lo planes
// ---------------------------------------------------------------------------
__global__ __launch_bounds__(256) void qk_prep_kernel(
    const float* __restrict__ Q, const float* __restrict__ K)
{
    int idx = blockIdx.x * 256 + threadIdx.x;   // 0 .. BH*2048*32-1
    const float2 q2 = *(const float2*)&Q[2 * (size_t)idx];
    const float2 k2 = *(const float2*)&K[2 * (size_t)idx];
    unsigned hi, lo;
    split_pack(q2.x, q2.y, hi, lo);
    g_Qh[idx] = hi; g_Ql[idx] = lo;
    split_pack(k2.x, k2.y, hi, lo);
    g_Kh[idx] = hi; g_Kl[idx] = lo;
}

// ---------------------------------------------------------------------------
// Kernel 0b: V -> packed transposed bf16 hi/lo planes [bh][chunk][d][kp]
// ---------------------------------------------------------------------------
__global__ __launch_bounds__(256) void v_prep_kernel(const float* __restrict__ V)
{
    __shared__ float Vs[64 * 68];
    int c  = blockIdx.x;
    int bh = blockIdx.y;
    int t  = threadIdx.x;
    const float* Vp = V + (size_t)bh * S_ * D_ + (size_t)c * 64 * D_;
    #pragma unroll
    for (int i = 0; i < 4; i++) {
        int idx = t + i * 256;
        int k = idx >> 4, d4 = idx & 15;
        *(float4*)&Vs[k * 68 + d4 * 4] = *(const float4*)&Vp[(size_t)k * D_ + d4 * 4];
    }
    __syncthreads();
    unsigned base = ((unsigned)bh * KBLK + c) * 64 * 32;
    #pragma unroll
    for (int i = 0; i < 8; i++) {
        int idx = t + i * 256;
        int d = idx >> 5, kp = idx & 31;
        unsigned hh, ll;
        split_pack(Vs[(2 * kp) * 68 + d], Vs[(2 * kp + 1) * 68 + d], hh, ll);
        g_Vth[base + d * 32 + kp] = hh;
        g_Vtl[base + d * 32 + kp] = ll;
    }
}

// ---------------------------------------------------------------------------
// Kernel 1: stats only. Tile 128(q) x 128(k), 8 warps (4m x 2n), no W store.
// ---------------------------------------------------------------------------
#define QSTR 36
#define L_QH 0
#define L_QL (128 * QSTR)
#define L_KH (2 * 128 * QSTR)
#define L_KL (3 * 128 * QSTR)
#define L_LUT (4 * 128 * QSTR)
#define L_SMEM ((L_LUT + 288) * 4)

__global__ __launch_bounds__(256, 2) void stats_kernel(
    const int* __restrict__ mask)
{
    extern __shared__ unsigned smu[];
    float* sLut = (float*)(smu + L_LUT);

    int bh = blockIdx.z;
    int q0 = blockIdx.y * 128;
    int k0 = blockIdx.x * 128;
    int b  = bh >> 3;
    int h  = bh & 7;

    int t = threadIdx.x;
    int w = t >> 5, l = t & 31, g = l >> 2, tg = l & 3;
    int wm = w & 3, wn = w >> 2;

    int lbase = k0 - q0 + 2048 - 128;
    for (int i = t; i < 288; i += 256) {
        int ix = lbase + i;
        ix = ix < 0 ? 0 : (ix > 4095 ? 4095 : ix);
        sLut[i] = g_bias_lut[h * 4096 + ix];
    }

    unsigned sbase = (unsigned)__cvta_generic_to_shared(smu);
    // cp.async fill: 128 rows x 8 granules per plane, 4 planes
    unsigned qrow = (unsigned)bh * S_ + q0;
    unsigned krow = (unsigned)bh * S_ + k0;
    #pragma unroll
    for (int i = 0; i < 4; i++) {
        int idx = t + i * 256;
        int r = idx >> 3, sg = idx & 7;
        cpa16(sbase + (L_QH + r * QSTR + sg * 4) * 4, &g_Qh[(qrow + r) * 32 + sg * 4]);
        cpa16(sbase + (L_QL + r * QSTR + sg * 4) * 4, &g_Ql[(qrow + r) * 32 + sg * 4]);
        cpa16(sbase + (L_KH + r * QSTR + sg * 4) * 4, &g_Kh[(krow + r) * 32 + sg * 4]);
        cpa16(sbase + (L_KL + r * QSTR + sg * 4) * 4, &g_Kl[(krow + r) * 32 + sg * 4]);
    }
    cpa_commit(); cpa_wait0();
    __syncthreads();

    int lq = l & 7, lh8 = (l >> 3) & 1, lc = (l >> 4);
    int qd = l >> 3;
    unsigned aoff = ((wm * 32 + lh8 * 8 + lq) * QSTR + lc * 4) * 4;
    unsigned boff = ((wn * 64 + (qd >> 1) * 8 + lq) * QSTR + (qd & 1) * 4) * 4;

    float C[2][8][4] = {};

    #pragma unroll
    for (int ks = 0; ks < 4; ks++) {
        unsigned ah[2][4], al[2][4];
        #pragma unroll
        for (int mt = 0; mt < 2; mt++) {
            ldm4(ah[mt], sbase + L_QH * 4 + aoff + mt * (16 * QSTR * 4) + ks * 32);
            ldm4(al[mt], sbase + L_QL * 4 + aoff + mt * (16 * QSTR * 4) + ks * 32);
        }
        #pragma unroll
        for (int ntp = 0; ntp < 4; ntp++) {
            unsigned bhf[4], blf[4];
            ldm4(bhf, sbase + L_KH * 4 + boff + ntp * (16 * QSTR * 4) + ks * 32);
            ldm4(blf, sbase + L_KL * 4 + boff + ntp * (16 * QSTR * 4) + ks * 32);
            #pragma unroll
            for (int mt = 0; mt < 2; mt++) {
                mma16(C[mt][2 * ntp],     ah[mt], bhf);
                mma16(C[mt][2 * ntp],     ah[mt], blf);
                mma16(C[mt][2 * ntp],     al[mt], bhf);
                mma16(C[mt][2 * ntp + 1], ah[mt], bhf + 2);
                mma16(C[mt][2 * ntp + 1], ah[mt], blf + 2);
                mma16(C[mt][2 * ntp + 1], al[mt], bhf + 2);
            }
        }
    }

    // finalize logits in regs (no store)
    #pragma unroll
    for (int nt = 0; nt < 8; nt++) {
        int kcol = k0 + wn * 64 + nt * 8 + 2 * tg;
        int jc = (kcol - k0) + 128;
        float mv0 = -1e9f * (float)mask[b * S_ + kcol];
        float mv1 = -1e9f * (float)mask[b * S_ + kcol + 1];
        #pragma unroll
        for (int mt = 0; mt < 2; mt++) {
            int q = q0 + wm * 32 + mt * 16 + g;
            int jq = jc - (q - q0);
            C[mt][nt][0] = C[mt][nt][0] * 0.125f + sLut[jq]     + mv0;
            C[mt][nt][1] = C[mt][nt][1] * 0.125f + sLut[jq + 1] + mv1;
            int jq2 = jq - 8;
            C[mt][nt][2] = C[mt][nt][2] * 0.125f + sLut[jq2]     + mv0;
            C[mt][nt][3] = C[mt][nt][3] * 0.125f + sLut[jq2 + 1] + mv1;
        }
    }

    float mxv[4], smv[4];
    #pragma unroll
    for (int ri = 0; ri < 4; ri++) {
        int mt = ri >> 1, hf = ri & 1;
        float m = -3.4e38f;
        #pragma unroll
        for (int nt = 0; nt < 8; nt++) {
            m = fmaxf(m, C[mt][nt][hf * 2]);
            m = fmaxf(m, C[mt][nt][hf * 2 + 1]);
        }
        m = fmaxf(m, __shfl_xor_sync(0xffffffffu, m, 1));
        m = fmaxf(m, __shfl_xor_sync(0xffffffffu, m, 2));
        float s = 0.f;
        #pragma unroll
        for (int nt = 0; nt < 8; nt++) {
            s += fast_exp(C[mt][nt][hf * 2]     - m);
            s += fast_exp(C[mt][nt][hf * 2 + 1] - m);
        }
        s += __shfl_xor_sync(0xffffffffu, s, 1);
        s += __shfl_xor_sync(0xffffffffu, s, 2);
        mxv[ri] = m; smv[ri] = s;
    }
    __syncthreads();

    float* sMax = (float*)smu;
    float* sSum = sMax + 256;
    if (tg == 0) {
        #pragma unroll
        for (int ri = 0; ri < 4; ri++) {
            int rl = wm * 32 + (ri >> 1) * 16 + (ri & 1) * 8 + g;
            sMax[rl * 2 + wn] = mxv[ri];
            sSum[rl * 2 + wn] = smv[ri];
        }
    }
    __syncthreads();
    if (t < 128) {
        float m0 = sMax[t * 2], m1 = sMax[t * 2 + 1];
        float M = fmaxf(m0, m1);
        float Sv = sSum[t * 2] * fast_exp(m0 - M) + sSum[t * 2 + 1] * fast_exp(m1 - M);
        g_stats[((size_t)bh * S_ + q0 + t) * QBLK + blockIdx.x] = make_float2(M, Sv);
    }
}

// ---------------------------------------------------------------------------
// Kernel 2: merge 16 block stats -> (rowmax, 1/rowsum)
// ---------------------------------------------------------------------------
__global__ __launch_bounds__(256) void reduce_kernel()
{
    int t = threadIdx.x;
    int wid = t >> 5, lane = t & 31;
    int row = blockIdx.x * 8 + wid;
    float2 st = (lane < QBLK) ? g_stats[(size_t)row * QBLK + lane]
                              : make_float2(-3.4e38f, 0.f);
    float M = st.x;
    #pragma unroll
    for (int o = 16; o; o >>= 1) M = fmaxf(M, __shfl_xor_sync(0xffffffffu, M, o));
    float Sv = st.y * fast_exp(st.x - M);
    #pragma unroll
    for (int o = 16; o; o >>= 1) Sv += __shfl_xor_sync(0xffffffffu, Sv, o);
    if (lane == 0) g_rowstats[row] = make_float2(M, 1.0f / Sv);
}

// ---------------------------------------------------------------------------
// Kernel 3: recompute QK^T per chunk, softmax-apply, write weights once, P@V.
// Block 64(q) x full K loop; 8 warps (4m x 2n); warp S-tile 16x32, O-tile 16x32.
// ---------------------------------------------------------------------------
#define PSTR 36
#define A_QH 0
#define A_QL 2304
#define A_KH 4608                   // 2 stages x 2304
#define A_KL 9216
#define A_VH 13824
#define A_VL 18432
#define A_PH 23040
#define A_PL 25344
#define A_ST 27648                  // sM[64], sI[64]
#define AV_SMEM ((A_ST + 128) * 4)  // 111104 B

__global__ __launch_bounds__(256, 2) void av_kernel(
    const int* __restrict__ mask, float* __restrict__ out)
{
    extern __shared__ unsigned smu[];
    float* sM = (float*)(smu + A_ST);
    float* sI = sM + 64;

    int bh = blockIdx.y;
    int q0 = blockIdx.x * 64;
    int b  = bh >> 3;
    int h  = bh & 7;

    float* Wp = out + OUT_OFF + (size_t)bh * S_ * S_;
    const float* lut = g_bias_lut + h * 4096 + 2048;

    int t = threadIdx.x;
    int w = t >> 5, l = t & 31, g = l >> 2, tg = l & 3;
    int wm = w & 3, wn = w >> 2;

    unsigned sbase = (unsigned)__cvta_generic_to_shared(smu);

    int lq = l & 7, lh8 = (l >> 3) & 1, lc = (l >> 4);
    int qd = l >> 3;
    unsigned aoff = ((wm * 16 + lh8 * 8 + lq) * PSTR + lc * 4) * 4;
    unsigned boff = (((qd >> 1) * 8 + lq) * PSTR + (qd & 1) * 4) * 4;   // + wn*32 rows added per use

    if (t < 64) {
        float2 rs = g_rowstats[(size_t)bh * S_ + q0 + t];
        sM[t] = rs.x; sI[t] = rs.y;
    }

    // Q planes (single fill)
    {
        unsigned qrow = (unsigned)bh * S_ + q0;
        #pragma unroll
        for (int i = 0; i < 2; i++) {
            int idx = t + i * 256;
            int r = idx >> 3, sg = idx & 7;
            cpa16(sbase + (A_QH + r * PSTR + sg * 4) * 4, &g_Qh[(qrow + r) * 32 + sg * 4]);
            cpa16(sbase + (A_QL + r * PSTR + sg * 4) * 4, &g_Ql[(qrow + r) * 32 + sg * 4]);
        }
    }
    // K/V chunk 0 into stage 0
    {
        unsigned krow = (unsigned)bh * S_;
        unsigned vb = (unsigned)bh * KBLK * 64 * 32;
        #pragma unroll
        for (int i = 0; i < 2; i++) {
            int idx = t + i * 256;
            int r = idx >> 3, sg = idx & 7;
            cpa16(sbase + (A_KH + r * PSTR + sg * 4) * 4, &g_Kh[(krow + r) * 32 + sg * 4]);
            cpa16(sbase + (A_KL + r * PSTR + sg * 4) * 4, &g_Kl[(krow + r) * 32 + sg * 4]);
            cpa16(sbase + (A_VH + r * PSTR + sg * 4) * 4, &g_Vth[vb + r * 32 + sg * 4]);
            cpa16(sbase + (A_VL + r * PSTR + sg * 4) * 4, &g_Vtl[vb + r * 32 + sg * 4]);
        }
        cpa_commit();
    }

    float C[4][4] = {};   // O accumulator

    for (int kci = 0; kci < KBLK; kci++) {
        int kc = kci * 64;
        int st = kci & 1;
        cpa_wait0();
        __syncthreads();

        if (kci + 1 < KBLK) {
            int s = (kci + 1) & 1;
            unsigned krow = (unsigned)bh * S_ + kc + 64;
            unsigned vb = ((unsigned)bh * KBLK + kci + 1) * 64 * 32;
            #pragma unroll
            for (int i = 0; i < 2; i++) {
                int idx = t + i * 256;
                int r = idx >> 3, sg = idx & 7;
                cpa16(sbase + (A_KH + s * 2304 + r * PSTR + sg * 4) * 4, &g_Kh[(krow + r) * 32 + sg * 4]);
                cpa16(sbase + (A_KL + s * 2304 + r * PSTR + sg * 4) * 4, &g_Kl[(krow + r) * 32 + sg * 4]);
                cpa16(sbase + (A_VH + s * 2304 + r * PSTR + sg * 4) * 4, &g_Vth[vb + r * 32 + sg * 4]);
                cpa16(sbase + (A_VL + s * 2304 + r * PSTR + sg * 4) * 4, &g_Vtl[vb + r * 32 + sg * 4]);
            }
            cpa_commit();
        }

        // --- recompute S = Q K^T for this chunk ---
        float Cs[4][4] = {};
        unsigned khb = (A_KH + st * 2304) * 4;
        unsigned klb = (A_KL + st * 2304) * 4;
        unsigned bwn = (wn * 32 * PSTR) * 4;
        #pragma unroll
        for (int ks = 0; ks < 4; ks++) {
            unsigned ah[4], al[4];
            ldm4(ah, sbase + A_QH * 4 + aoff + ks * 32);
            ldm4(al, sbase + A_QL * 4 + aoff + ks * 32);
            #pragma unroll
            for (int ntp = 0; ntp < 2; ntp++) {
                unsigned bhf[4], blf[4];
                ldm4(bhf, sbase + khb + bwn + boff + ntp * (16 * PSTR * 4) + ks * 32);
                ldm4(blf, sbase + klb + bwn + boff + ntp * (16 * PSTR * 4) + ks * 32);
                mma16(Cs[2 * ntp],     ah, bhf);
                mma16(Cs[2 * ntp],     ah, blf);
                mma16(Cs[2 * ntp],     al, bhf);
                mma16(Cs[2 * ntp + 1], ah, bhf + 2);
                mma16(Cs[2 * ntp + 1], ah, blf + 2);
                mma16(Cs[2 * ntp + 1], al, bhf + 2);
            }
        }

        // --- epilogue: bias+mask+exp, write weights, pack P ---
        int rlo = wm * 16 + g;
        float Mlo = sM[rlo] * LOG2E, Ilo = sI[rlo];
        float Mhi = sM[rlo + 8] * LOG2E, Ihi = sI[rlo + 8];
        #pragma unroll
        for (int nt = 0; nt < 4; nt++) {
            int kcol = kc + wn * 32 + nt * 8 + 2 * tg;
            float mv0 = -1e9f * (float)__ldg(&mask[b * S_ + kcol]);
            float mv1 = -1e9f * (float)__ldg(&mask[b * S_ + kcol + 1]);
            int qlo = q0 + rlo, qhi = qlo + 8;
            float x0 = fmaf(Cs[nt][0], 0.125f, __ldg(&lut[kcol - qlo])     + mv0);
            float x1 = fmaf(Cs[nt][1], 0.125f, __ldg(&lut[kcol + 1 - qlo]) + mv1);
            float x2 = fmaf(Cs[nt][2], 0.125f, __ldg(&lut[kcol - qhi])     + mv0);
            float x3 = fmaf(Cs[nt][3], 0.125f, __ldg(&lut[kcol + 1 - qhi]) + mv1);
            float p0 = ex2f(fmaf(x0, LOG2E, -Mlo)) * Ilo;
            float p1 = ex2f(fmaf(x1, LOG2E, -Mlo)) * Ilo;
            float p2 = ex2f(fmaf(x2, LOG2E, -Mhi)) * Ihi;
            float p3 = ex2f(fmaf(x3, LOG2E, -Mhi)) * Ihi;
            *(float2*)&Wp[(size_t)qlo * S_ + kcol] = make_float2(p0, p1);
            *(float2*)&Wp[(size_t)qhi * S_ + kcol] = make_float2(p2, p3);
            unsigned hh, ll;
            int pc = wn * 16 + nt * 4 + tg;
            split_pack(p0, p1, hh, ll);
            smu[A_PH + rlo * PSTR + pc] = hh;
            smu[A_PL + rlo * PSTR + pc] = ll;
            split_pack(p2, p3, hh, ll);
            smu[A_PH + (rlo + 8) * PSTR + pc] = hh;
            smu[A_PL + (rlo + 8) * PSTR + pc] = ll;
        }
        __syncthreads();

        // --- P @ V ---
        unsigned vhb = (A_VH + st * 2304) * 4;
        unsigned vlb = (A_VL + st * 2304) * 4;
        #pragma unroll
        for (int ks = 0; ks < 4; ks++) {
            unsigned ah[4], al[4];
            ldm4(ah, sbase + A_PH * 4 + aoff + ks * 32);
            ldm4(al, sbase + A_PL * 4 + aoff + ks * 32);
            #pragma unroll
            for (int ntp = 0; ntp < 2; ntp++) {
                unsigned bhf[4], blf[4];
                ldm4(bhf, sbase + vhb + bwn + boff + ntp * (16 * PSTR * 4) + ks * 32);
                ldm4(blf, sbase + vlb + bwn + boff + ntp * (16 * PSTR * 4) + ks * 32);
                mma16(C[2 * ntp],     ah, bhf);
                mma16(C[2 * ntp],     ah, blf);
                mma16(C[2 * ntp],     al, bhf);
                mma16(C[2 * ntp + 1], ah, bhf + 2);
                mma16(C[2 * ntp + 1], ah, blf + 2);
                mma16(C[2 * ntp + 1], al, bhf + 2);
            }
        }
        __syncthreads();
    }

    #pragma unroll
    for (int nt = 0; nt < 4; nt++) {
        int d = wn * 32 + nt * 8 + 2 * tg;
        int q = q0 + wm * 16 + g;
        *(float2*)&out[((size_t)bh * S_ + q) * D_ + d]     = make_float2(C[nt][0], C[nt][1]);
        *(float2*)&out[((size_t)bh * S_ + q + 8) * D_ + d] = make_float2(C[nt][2], C[nt][3]);
    }
}

// ---------------------------------------------------------------------------
extern "C" void kernel_launch(void* const* d_in, const int* in_sizes, int n_in,
                              void* d_out, int out_size)
{
    const float* Q    = (const float*)d_in[0];
    const float* K    = (const float*)d_in[1];
    const float* V    = (const float*)d_in[2];
    const int*   mask = (const int*)d_in[3];
    const float* bt   = (const float*)d_in[4];
    float* out = (float*)d_out;

    cudaFuncSetAttribute(stats_kernel, cudaFuncAttributeMaxDynamicSharedMemorySize, L_SMEM);
    cudaFuncSetAttribute(av_kernel,    cudaFuncAttributeMaxDynamicSharedMemorySize, AV_SMEM);

    bias_lut_kernel<<<32, 1024>>>(bt);
    qk_prep_kernel<<<BH_ * S_ * 32 / 256, 256>>>(Q, K);
    dim3 gv(KBLK, BH_);
    v_prep_kernel<<<gv, 256>>>(V);

    dim3 g1(S_ / 128, S_ / 128, BH_);   // (16, 16, 16)
    stats_kernel<<<g1, 256, L_SMEM>>>(mask);

    reduce_kernel<<<BH_ * S_ / 8, 256>>>();

    dim3 g2(S_ / 64, BH_);              // (32, 16)
    av_kernel<<<g2, 256, AV_SMEM>>>(mask, out);
}

// round 10
// speedup vs baseline: 1.2306x; 1.2306x over previous
#include <cuda_runtime.h>
#include <cuda_bf16.h>
#include <cstdint>

#define B_ 2
#define H_ 8
#define S_ 2048
#define D_ 64
#define BH_ (B_ * H_)
#define OUT_OFF ((size_t)B_ * H_ * S_ * D_)   // output tensor first, then weights
#define KBLK 32                                // av chunks (64 wide)
#define QBLK 16                                // logits k-blocks (128 wide)

__device__ float  g_bias_lut[H_ * 2 * S_];
__device__ float  g_sums[BH_ * S_ * QBLK];    // per (row, 128-kblock) partial expsum
// packed bf16 hi/lo planes
__device__ unsigned g_Qh[BH_ * S_ * 32];
__device__ unsigned g_Ql[BH_ * S_ * 32];
__device__ unsigned g_Kh[BH_ * S_ * 32];
__device__ unsigned g_Kl[BH_ * S_ * 32];
__device__ unsigned g_Vth[BH_ * KBLK * 64 * 32];   // [bh][chunk][d][kpair]
__device__ unsigned g_Vtl[BH_ * KBLK * 64 * 32];

// ---- helpers ----------------------------------------------------------------
__device__ __forceinline__ void split_pack(float x0, float x1, unsigned& hi, unsigned& lo) {
    __nv_bfloat162 h = __floats2bfloat162_rn(x0, x1);
    float f0 = __bfloat162float(__low2bfloat16(h));
    float f1 = __bfloat162float(__high2bfloat16(h));
    __nv_bfloat162 l = __floats2bfloat162_rn(x0 - f0, x1 - f1);
    hi = *reinterpret_cast<unsigned*>(&h);
    lo = *reinterpret_cast<unsigned*>(&l);
}
__device__ __forceinline__ void mma16(float* d, const unsigned* a, const unsigned* b) {
    asm("mma.sync.aligned.m16n8k16.row.col.f32.bf16.bf16.f32 "
        "{%0,%1,%2,%3},{%4,%5,%6,%7},{%8,%9},{%0,%1,%2,%3};"
        : "+f"(d[0]), "+f"(d[1]), "+f"(d[2]), "+f"(d[3])
        : "r"(a[0]), "r"(a[1]), "r"(a[2]), "r"(a[3]), "r"(b[0]), "r"(b[1]));
}
__device__ __forceinline__ void ldm4(unsigned* r, unsigned addr) {
    asm volatile("ldmatrix.sync.aligned.m8n8.x4.shared.b16 {%0,%1,%2,%3}, [%4];"
        : "=r"(r[0]), "=r"(r[1]), "=r"(r[2]), "=r"(r[3]) : "r"(addr));
}
__device__ __forceinline__ void cpa16(unsigned dst, const void* src) {
    asm volatile("cp.async.cg.shared.global [%0], [%1], 16;" :: "r"(dst), "l"(src));
}
__device__ __forceinline__ void cpa_commit() { asm volatile("cp.async.commit_group;"); }
__device__ __forceinline__ void cpa_wait0()  { asm volatile("cp.async.wait_group 0;"); }
__device__ __forceinline__ float ex2f(float x) {
    float r; asm("ex2.approx.f32 %0, %1;" : "=f"(r) : "f"(x)); return r;
}
#define LOG2E 1.4426950408889634f
// exp without max-subtraction; clamp input so ex2.approx stays in range
__device__ __forceinline__ float exp_nomax(float x) {
    return ex2f(fmaxf(x * LOG2E, -126.0f));
}

// ---------------------------------------------------------------------------
// Kernel 0: T5 bias LUT (exact integer bucket thresholds)
// ---------------------------------------------------------------------------
__global__ void bias_lut_kernel(const float* __restrict__ bias_table) {
    int idx = blockIdx.x * blockDim.x + threadIdx.x;
    if (idx >= H_ * 2 * S_) return;
    int h   = idx >> 12;
    int r   = idx & 4095;
    int rel = r - 2048;
    int bucket = (rel > 0) ? 16 : 0;
    int a = rel < 0 ? -rel : rel;
    int add;
    if      (a <  8) add = a;
    else if (a < 12) add = 8;
    else if (a < 16) add = 9;
    else if (a < 23) add = 10;
    else if (a < 32) add = 11;
    else if (a < 46) add = 12;
    else if (a < 64) add = 13;
    else if (a < 91) add = 14;
    else             add = 15;
    g_bias_lut[idx] = bias_table[(bucket + add) * H_ + h];
}

// ---------------------------------------------------------------------------
// Kernel 0a: Q,K -> packed row-major bf16 hi/lo planes
// ---------------------------------------------------------------------------
__global__ __launch_bounds__(256) void qk_prep_kernel(
    const float* __restrict__ Q, const float* __restrict__ K)
{
    int idx = blockIdx.x * 256 + threadIdx.x;
    const float2 q2 = *(const float2*)&Q[2 * (size_t)idx];
    const float2 k2 = *(const float2*)&K[2 * (size_t)idx];
    unsigned hi, lo;
    split_pack(q2.x, q2.y, hi, lo);
    g_Qh[idx] = hi; g_Ql[idx] = lo;
    split_pack(k2.x, k2.y, hi, lo);
    g_Kh[idx] = hi; g_Kl[idx] = lo;
}

// ---------------------------------------------------------------------------
// Kernel 0b: V -> packed transposed bf16 hi/lo planes [bh][chunk][d][kp]
// ---------------------------------------------------------------------------
__global__ __launch_bounds__(256) void v_prep_kernel(const float* __restrict__ V)
{
    __shared__ float Vs[64 * 68];
    int c  = blockIdx.x;
    int bh = blockIdx.y;
    int t  = threadIdx.x;
    const float* Vp = V + (size_t)bh * S_ * D_ + (size_t)c * 64 * D_;
    #pragma unroll
    for (int i = 0; i < 4; i++) {
        int idx = t + i * 256;
        int k = idx >> 4, d4 = idx & 15;
        *(float4*)&Vs[k * 68 + d4 * 4] = *(const float4*)&Vp[(size_t)k * D_ + d4 * 4];
    }
    __syncthreads();
    unsigned base = ((unsigned)bh * KBLK + c) * 64 * 32;
    #pragma unroll
    for (int i = 0; i < 8; i++) {
        int idx = t + i * 256;
        int d = idx >> 5, kp = idx & 31;
        unsigned hh, ll;
        split_pack(Vs[(2 * kp) * 68 + d], Vs[(2 * kp + 1) * 68 + d], hh, ll);
        g_Vth[base + d * 32 + kp] = hh;
        g_Vtl[base + d * 32 + kp] = ll;
    }
}

// ---------------------------------------------------------------------------
// Kernel 1: writes expW = exp(QK^T/8 + bias + mask*-1e9) (no max) + partial
// row sums. Tile 128(q) x 128(k), 8 warps (4m x 2n), cp.async plane fill.
// ---------------------------------------------------------------------------
#define QSTR 36
#define L_QH 0
#define L_QL (128 * QSTR)
#define L_KH (2 * 128 * QSTR)
#define L_KL (3 * 128 * QSTR)
#define L_LUT (4 * 128 * QSTR)
#define L_SMEM ((L_LUT + 288) * 4)

__global__ __launch_bounds__(256, 2) void logits_kernel(
    const int* __restrict__ mask, float* __restrict__ out)
{
    extern __shared__ unsigned smu[];
    float* sLut = (float*)(smu + L_LUT);

    int bh = blockIdx.z;
    int q0 = blockIdx.y * 128;
    int k0 = blockIdx.x * 128;
    int b  = bh >> 3;
    int h  = bh & 7;

    int t = threadIdx.x;
    int w = t >> 5, l = t & 31, g = l >> 2, tg = l & 3;
    int wm = w & 3, wn = w >> 2;

    int lbase = k0 - q0 + 2048 - 128;
    for (int i = t; i < 288; i += 256) {
        int ix = lbase + i;
        ix = ix < 0 ? 0 : (ix > 4095 ? 4095 : ix);
        sLut[i] = g_bias_lut[h * 4096 + ix];
    }

    unsigned sbase = (unsigned)__cvta_generic_to_shared(smu);
    unsigned qrow = (unsigned)bh * S_ + q0;
    unsigned krow = (unsigned)bh * S_ + k0;
    #pragma unroll
    for (int i = 0; i < 4; i++) {
        int idx = t + i * 256;
        int r = idx >> 3, sg = idx & 7;
        cpa16(sbase + (L_QH + r * QSTR + sg * 4) * 4, &g_Qh[(qrow + r) * 32 + sg * 4]);
        cpa16(sbase + (L_QL + r * QSTR + sg * 4) * 4, &g_Ql[(qrow + r) * 32 + sg * 4]);
        cpa16(sbase + (L_KH + r * QSTR + sg * 4) * 4, &g_Kh[(krow + r) * 32 + sg * 4]);
        cpa16(sbase + (L_KL + r * QSTR + sg * 4) * 4, &g_Kl[(krow + r) * 32 + sg * 4]);
    }
    cpa_commit(); cpa_wait0();
    __syncthreads();

    int lq = l & 7, lh8 = (l >> 3) & 1, lc = (l >> 4);
    int qd = l >> 3;
    unsigned aoff = ((wm * 32 + lh8 * 8 + lq) * QSTR + lc * 4) * 4;
    unsigned boff = ((wn * 64 + (qd >> 1) * 8 + lq) * QSTR + (qd & 1) * 4) * 4;

    float C[2][8][4] = {};

    #pragma unroll
    for (int ks = 0; ks < 4; ks++) {
        unsigned ah[2][4], al[2][4];
        #pragma unroll
        for (int mt = 0; mt < 2; mt++) {
            ldm4(ah[mt], sbase + L_QH * 4 + aoff + mt * (16 * QSTR * 4) + ks * 32);
            ldm4(al[mt], sbase + L_QL * 4 + aoff + mt * (16 * QSTR * 4) + ks * 32);
        }
        #pragma unroll
        for (int ntp = 0; ntp < 4; ntp++) {
            unsigned bhf[4], blf[4];
            ldm4(bhf, sbase + L_KH * 4 + boff + ntp * (16 * QSTR * 4) + ks * 32);
            ldm4(blf, sbase + L_KL * 4 + boff + ntp * (16 * QSTR * 4) + ks * 32);
            #pragma unroll
            for (int mt = 0; mt < 2; mt++) {
                mma16(C[mt][2 * ntp],     ah[mt], bhf);
                mma16(C[mt][2 * ntp],     ah[mt], blf);
                mma16(C[mt][2 * ntp],     al[mt], bhf);
                mma16(C[mt][2 * ntp + 1], ah[mt], bhf + 2);
                mma16(C[mt][2 * ntp + 1], ah[mt], blf + 2);
                mma16(C[mt][2 * ntp + 1], al[mt], bhf + 2);
            }
        }
    }

    // epilogue: x -> exp(x), store expW, accumulate row sums
    float* wbase = out + OUT_OFF + (size_t)bh * S_ * S_;
    float rsum[4] = {0.f, 0.f, 0.f, 0.f};   // [mt*2 + hf]
    #pragma unroll
    for (int nt = 0; nt < 8; nt++) {
        int kcol = k0 + wn * 64 + nt * 8 + 2 * tg;
        int jc = (kcol - k0) + 128;
        float mv0 = -1e9f * (float)mask[b * S_ + kcol];
        float mv1 = -1e9f * (float)mask[b * S_ + kcol + 1];
        #pragma unroll
        for (int mt = 0; mt < 2; mt++) {
            int q = q0 + wm * 32 + mt * 16 + g;
            int jq = jc - (q - q0);
            float e0 = exp_nomax(fmaf(C[mt][nt][0], 0.125f, sLut[jq]     + mv0));
            float e1 = exp_nomax(fmaf(C[mt][nt][1], 0.125f, sLut[jq + 1] + mv1));
            *(float2*)&wbase[(size_t)q * S_ + kcol] = make_float2(e0, e1);
            int jq2 = jq - 8;
            float e2 = exp_nomax(fmaf(C[mt][nt][2], 0.125f, sLut[jq2]     + mv0));
            float e3 = exp_nomax(fmaf(C[mt][nt][3], 0.125f, sLut[jq2 + 1] + mv1));
            *(float2*)&wbase[(size_t)(q + 8) * S_ + kcol] = make_float2(e2, e3);
            rsum[mt * 2]     += e0 + e1;
            rsum[mt * 2 + 1] += e2 + e3;
        }
    }
    #pragma unroll
    for (int ri = 0; ri < 4; ri++) {
        rsum[ri] += __shfl_xor_sync(0xffffffffu, rsum[ri], 1);
        rsum[ri] += __shfl_xor_sync(0xffffffffu, rsum[ri], 2);
    }
    __syncthreads();   // smem reuse barrier

    float* sSum = (float*)smu;   // [128][2]
    if (tg == 0) {
        #pragma unroll
        for (int ri = 0; ri < 4; ri++) {
            int rl = wm * 32 + (ri >> 1) * 16 + (ri & 1) * 8 + g;
            sSum[rl * 2 + wn] = rsum[ri];
        }
    }
    __syncthreads();
    if (t < 128)
        g_sums[((size_t)bh * S_ + q0 + t) * QBLK + blockIdx.x] = sSum[t * 2] + sSum[t * 2 + 1];
}

// ---------------------------------------------------------------------------
// Kernel 2: av. Reads expW (cp.async double-buffered), scales by invS,
// writes normalized weights once, P@V via ldmatrix + bf16 3-term mma.
// ---------------------------------------------------------------------------
#define PSTR 36
#define RAWSTR 68
#define OFF_RAW   0
#define OFF_PH    (2 * 64 * RAWSTR)
#define OFF_PL    (OFF_PH + 64 * PSTR)
#define OFF_VH    (OFF_PL + 64 * PSTR)
#define OFF_VL    (OFF_VH + 2 * 64 * PSTR)
#define OFF_ST    (OFF_VL + 2 * 64 * PSTR)
#define AV_SMEM   ((OFF_ST + 64) * 4)

__global__ __launch_bounds__(256) void av_kernel(
    float* __restrict__ W, float* __restrict__ out)
{
    extern __shared__ unsigned smu[];
    float*    rawW = (float*)smu;
    unsigned* Ph   = smu + OFF_PH;
    unsigned* Pl   = smu + OFF_PL;
    float*    sI   = (float*)(smu + OFF_ST);

    int bh = blockIdx.y;
    int q0 = blockIdx.x * 64;

    float* Wp = W + OUT_OFF + (size_t)bh * S_ * S_;

    int t = threadIdx.x;
    int w = t >> 5, l = t & 31, g = l >> 2, tg = l & 3;
    int wm = w & 3, wn = w >> 2;

    unsigned sbase = (unsigned)__cvta_generic_to_shared(smu);

    int lq = l & 7, lh8 = (l >> 3) & 1, lc = (l >> 4);
    int qd = l >> 3;
    unsigned aoff = ((wm * 16 + lh8 * 8 + lq) * PSTR + lc * 4) * 4;
    unsigned boff = ((wn * 32 + (qd >> 1) * 8 + lq) * PSTR + (qd & 1) * 4) * 4;

    // invS per row from 16 partial sums
    if (t < 64) {
        const float* ps = &g_sums[((size_t)bh * S_ + q0 + t) * QBLK];
        float s = 0.f;
        #pragma unroll
        for (int i = 0; i < QBLK; i++) s += ps[i];
        sI[t] = 1.0f / s;
    }

    // prefetch chunk 0 into stage 0
    {
        #pragma unroll
        for (int i = 0; i < 4; i++) {
            int idx = t + i * 256;
            int r = idx >> 4, c4 = idx & 15;
            cpa16(sbase + (OFF_RAW + r * RAWSTR + c4 * 4) * 4,
                  &Wp[(size_t)(q0 + r) * S_ + c4 * 4]);
        }
        unsigned vb = (unsigned)bh * KBLK * 64 * 32;
        #pragma unroll
        for (int i = 0; i < 2; i++) {
            int idx = t + i * 256;
            int d = idx >> 3, sg = idx & 7;
            cpa16(sbase + (OFF_VH + d * PSTR + sg * 4) * 4, &g_Vth[vb + d * 32 + sg * 4]);
            cpa16(sbase + (OFF_VL + d * PSTR + sg * 4) * 4, &g_Vtl[vb + d * 32 + sg * 4]);
        }
        cpa_commit();
    }

    float C[4][4] = {};

    for (int kci = 0; kci < KBLK; kci++) {
        int kc = kci * 64;
        int st = kci & 1;
        cpa_wait0();
        __syncthreads();

        if (kci + 1 < KBLK) {
            int s = (kci + 1) & 1;
            #pragma unroll
            for (int i = 0; i < 4; i++) {
                int idx = t + i * 256;
                int r = idx >> 4, c4 = idx & 15;
                cpa16(sbase + (OFF_RAW + s * 64 * RAWSTR + r * RAWSTR + c4 * 4) * 4,
                      &Wp[(size_t)(q0 + r) * S_ + kc + 64 + c4 * 4]);
            }
            unsigned vb = ((unsigned)bh * KBLK + kci + 1) * 64 * 32;
            #pragma unroll
            for (int i = 0; i < 2; i++) {
                int idx = t + i * 256;
                int d = idx >> 3, sg = idx & 7;
                cpa16(sbase + (OFF_VH + s * 64 * PSTR + d * PSTR + sg * 4) * 4,
                      &g_Vth[vb + d * 32 + sg * 4]);
                cpa16(sbase + (OFF_VL + s * 64 * PSTR + d * PSTR + sg * 4) * 4,
                      &g_Vtl[vb + d * 32 + sg * 4]);
            }
            cpa_commit();
        }

        // fill P: p = expW * invS; write normalized; pack
        #pragma unroll
        for (int i = 0; i < 4; i++) {
            int idx = t + i * 256;
            int q = idx >> 4, f4 = idx & 15;
            float4 wv = *(const float4*)&rawW[st * 64 * RAWSTR + q * RAWSTR + f4 * 4];
            float I = sI[q];
            float p0 = wv.x * I, p1 = wv.y * I, p2 = wv.z * I, p3 = wv.w * I;
            *(float4*)&Wp[(size_t)(q0 + q) * S_ + kc + f4 * 4] = make_float4(p0, p1, p2, p3);
            unsigned h0, l0, h1, l1;
            split_pack(p0, p1, h0, l0);
            split_pack(p2, p3, h1, l1);
            *(uint2*)&Ph[q * PSTR + 2 * f4] = make_uint2(h0, h1);
            *(uint2*)&Pl[q * PSTR + 2 * f4] = make_uint2(l0, l1);
        }
        __syncthreads();

        unsigned vhb = (OFF_VH + st * 64 * PSTR) * 4;
        unsigned vlb = (OFF_VL + st * 64 * PSTR) * 4;
        #pragma unroll
        for (int ks = 0; ks < 4; ks++) {
            unsigned ah[4], al[4];
            ldm4(ah, sbase + OFF_PH * 4 + aoff + ks * 32);
            ldm4(al, sbase + OFF_PL * 4 + aoff + ks * 32);
            #pragma unroll
            for (int ntp = 0; ntp < 2; ntp++) {
                unsigned bhf[4], blf[4];
                ldm4(bhf, sbase + vhb + boff + ntp * (16 * PSTR * 4) + ks * 32);
                ldm4(blf, sbase + vlb + boff + ntp * (16 * PSTR * 4) + ks * 32);
                mma16(C[2 * ntp],     ah, bhf);
                mma16(C[2 * ntp],     ah, blf);
                mma16(C[2 * ntp],     al, bhf);
                mma16(C[2 * ntp + 1], ah, bhf + 2);
                mma16(C[2 * ntp + 1], ah, blf + 2);
                mma16(C[2 * ntp + 1], al, bhf + 2);
            }
        }
        __syncthreads();
    }

    #pragma unroll
    for (int nt = 0; nt < 4; nt++) {
        int d = wn * 32 + nt * 8 + 2 * tg;
        int q = q0 + wm * 16 + g;
        *(float2*)&out[((size_t)bh * S_ + q) * D_ + d]     = make_float2(C[nt][0], C[nt][1]);
        *(float2*)&out[((size_t)bh * S_ + q + 8) * D_ + d] = make_float2(C[nt][2], C[nt][3]);
    }
}

// ---------------------------------------------------------------------------
extern "C" void kernel_launch(void* const* d_in, const int* in_sizes, int n_in,
                              void* d_out, int out_size)
{
    const float* Q    = (const float*)d_in[0];
    const float* K    = (const float*)d_in[1];
    const float* V    = (const float*)d_in[2];
    const int*   mask = (const int*)d_in[3];
    const float* bt   = (const float*)d_in[4];
    float* out = (float*)d_out;

    cudaFuncSetAttribute(logits_kernel, cudaFuncAttributeMaxDynamicSharedMemorySize, L_SMEM);
    cudaFuncSetAttribute(av_kernel,     cudaFuncAttributeMaxDynamicSharedMemorySize, AV_SMEM);

    bias_lut_kernel<<<32, 1024>>>(bt);
    qk_prep_kernel<<<BH_ * S_ * 32 / 256, 256>>>(Q, K);
    dim3 gv(KBLK, BH_);
    v_prep_kernel<<<gv, 256>>>(V);

    dim3 g1(S_ / 128, S_ / 128, BH_);   // (16, 16, 16)
    logits_kernel<<<g1, 256, L_SMEM>>>(mask, out);

    dim3 g2(S_ / 64, BH_);              // (32, 16)
    av_kernel<<<g2, 256, AV_SMEM>>>(out, out);
}